// round 2
// baseline (speedup 1.0000x reference)
#include <cuda_runtime.h>
#include <cstddef>

#define HH 320
#define WW 320
#define CC 64
#define BB 2
#define HW (HH*WW)              // 102400
#define CHW ((size_t)CC*HW)     // 6553600
#define TENSOR_ELEMS (BB*CHW)   // 13107200

#define QT 32
#define ROWP 324                // padded row stride (floats) for smem rows

typedef unsigned long long u64;

__device__ __forceinline__ u64 pack2(float lo, float hi) {
    u64 r; asm("mov.b64 %0, {%1,%2};" : "=l"(r) : "f"(lo), "f"(hi)); return r;
}
__device__ __forceinline__ void fma2(u64& d, u64 a, u64 b) {
    asm("fma.rn.f32x2 %0, %1, %2, %3;" : "=l"(d) : "l"(a), "l"(b), "l"(d));
}
__device__ __forceinline__ float2 unpack2(u64 v) {
    float2 f; asm("mov.b64 {%0,%1}, %2;" : "=f"(f.x), "=f"(f.y) : "l"(v)); return f;
}

// Scratch (static device arrays; no allocation allowed)
__device__ float g_M[2*CC*CC];           // M_ud, M_du (64x64 each)
__device__ float g_buf[2][TENSOR_ELEMS]; // buffer_d, buffer_u
__device__ float g_t[2][TENSOR_ELEMS];   // relu(conv1) intermediates

// ---------------------------------------------------------------------------
// Kernel 1: M[a][b] = sum_c Wq[c][a] * Wk[c][b]   (64x64)
// ---------------------------------------------------------------------------
__global__ void kcomputeM(const float* __restrict__ Wq,
                          const float* __restrict__ Wk, int dir) {
    __shared__ float sq[64*64];
    __shared__ float sk[64*64];
    int t = threadIdx.x;
    for (int i = t; i < 4096; i += 256) { sq[i] = Wq[i]; sk[i] = Wk[i]; }
    __syncthreads();
    for (int i = t; i < 4096; i += 256) {
        int a = i >> 6, b = i & 63;
        float s = 0.f;
        #pragma unroll 16
        for (int c = 0; c < 64; c++) s += sq[c*64 + a] * sk[c*64 + b];
        g_M[dir*4096 + i] = s;
    }
}

// ---------------------------------------------------------------------------
// Kernel 2: fused axial attention, both directions, one block per (b,h).
// ---------------------------------------------------------------------------
#define ATTN_SMEM ((64*ROWP*2 + QT*ROWP + 2048 + 4096) * 4)

__global__ __launch_bounds__(256)
void kattn(const float* __restrict__ u, const float* __restrict__ d) {
    extern __shared__ float smem[];
    float* su = smem;
    float* sd = su + 64*ROWP;
    float* sS = sd + 64*ROWP;
    float* sr = sS + QT*ROWP;
    float* sM = sr + 2048;

    int tid  = threadIdx.x;
    int lane = tid & 31, warp = tid >> 5;
    int b = blockIdx.x / HH, h = blockIdx.x % HH;
    const float* ubase = u + (size_t)b*CHW + (size_t)h*WW;
    const float* dbase = d + (size_t)b*CHW + (size_t)h*WW;

    for (int i = tid; i < 64*WW; i += 256) {
        int c = i / WW, w = i % WW;
        su[c*ROWP + w] = ubase[(size_t)c*HW + w];
        sd[c*ROWP + w] = dbase[(size_t)c*HW + w];
    }
    __syncthreads();

    for (int dir = 0; dir < 2; dir++) {
        const float* Mg = g_M + dir*4096;
        for (int i = tid; i < 4096; i += 256) sM[i] = Mg[i];
        float* sQ = (dir == 0) ? su : sd;   // query source row
        float* sV = (dir == 0) ? sd : su;   // key/value source row
        float* outg = g_buf[dir] + (size_t)b*CHW + (size_t)h*WW;
        __syncthreads();

        for (int q0 = 0; q0 < WW; q0 += QT) {
            // r[bb][q] = sum_a sQ[a][q0+q] * M[a][bb]
            for (int i = tid; i < 64*QT; i += 256) {
                int bb = i >> 5, q = i & 31;
                float s = 0.f;
                #pragma unroll 8
                for (int a = 0; a < 64; a++)
                    s += sQ[a*ROWP + q0 + q] * sM[a*64 + bb];
                sr[i] = s;
            }
            __syncthreads();

            // scores (packed f32x2): warp -> rows q=warp*4..+3, lane -> v = 2*lane + 64*j
            u64 acc2[4][5];
            #pragma unroll
            for (int i = 0; i < 4; i++)
                #pragma unroll
                for (int j = 0; j < 5; j++) acc2[i][j] = 0ull;
            for (int bb = 0; bb < 64; bb++) {
                u64 rv2[4];
                #pragma unroll
                for (int i = 0; i < 4; i++) {
                    float r = sr[bb*QT + warp*4 + i];
                    rv2[i] = pack2(r, r);
                }
                #pragma unroll
                for (int j = 0; j < 5; j++) {
                    u64 dv = *(const u64*)&sV[bb*ROWP + 2*lane + 64*j];
                    #pragma unroll
                    for (int i = 0; i < 4; i++) fma2(acc2[i][j], rv2[i], dv);
                }
            }
            // exact softmax per row (row lives in one warp)
            #pragma unroll
            for (int i = 0; i < 4; i++) {
                float2 f[5];
                #pragma unroll
                for (int j = 0; j < 5; j++) f[j] = unpack2(acc2[i][j]);
                float m = f[0].x;
                #pragma unroll
                for (int j = 0; j < 5; j++) { m = fmaxf(m, f[j].x); m = fmaxf(m, f[j].y); }
                #pragma unroll
                for (int o = 16; o > 0; o >>= 1) m = fmaxf(m, __shfl_xor_sync(~0u, m, o));
                float s = 0.f;
                #pragma unroll
                for (int j = 0; j < 5; j++) {
                    f[j].x = __expf(f[j].x - m); f[j].y = __expf(f[j].y - m);
                    s += f[j].x + f[j].y;
                }
                #pragma unroll
                for (int o = 16; o > 0; o >>= 1) s += __shfl_xor_sync(~0u, s, o);
                float inv = 1.f / s;
                #pragma unroll
                for (int j = 0; j < 5; j++) {
                    float2 w2 = make_float2(f[j].x*inv, f[j].y*inv);
                    *(float2*)&sS[(warp*4 + i)*ROWP + 2*lane + 64*j] = w2;
                }
            }
            __syncthreads();

            // attend (packed): out[c][q] = sum_v P[q][v]*sV[c][v]; v split in 2 halves
            {
                int half = tid >> 7;
                int t2 = tid & 127;
                int qg = t2 & 7;       // q = qg + 8*iq
                int cg = t2 >> 3;      // c = cg + 16*ic
                u64 oacc2[4][4];
                #pragma unroll
                for (int ic = 0; ic < 4; ic++)
                    #pragma unroll
                    for (int iq = 0; iq < 4; iq++) oacc2[ic][iq] = 0ull;
                int vbeg = half*160;
                for (int v = vbeg; v < vbeg + 160; v += 4) {
                    float4 pv[4], vv[4];
                    #pragma unroll
                    for (int iq = 0; iq < 4; iq++)
                        pv[iq] = *(const float4*)&sS[(qg + 8*iq)*ROWP + v];
                    #pragma unroll
                    for (int ic = 0; ic < 4; ic++)
                        vv[ic] = *(const float4*)&sV[(cg + 16*ic)*ROWP + v];
                    #pragma unroll
                    for (int ic = 0; ic < 4; ic++) {
                        const u64* vl = (const u64*)&vv[ic];
                        #pragma unroll
                        for (int iq = 0; iq < 4; iq++) {
                            const u64* pl = (const u64*)&pv[iq];
                            fma2(oacc2[ic][iq], vl[0], pl[0]);
                            fma2(oacc2[ic][iq], vl[1], pl[1]);
                        }
                    }
                }
                if (half == 0) {
                    #pragma unroll
                    for (int ic = 0; ic < 4; ic++)
                        #pragma unroll
                        for (int iq = 0; iq < 4; iq++) {
                            float2 f = unpack2(oacc2[ic][iq]);
                            sr[(cg + 16*ic)*QT + (qg + 8*iq)] = f.x + f.y;
                        }
                }
                __syncthreads();
                if (half == 1) {
                    #pragma unroll
                    for (int ic = 0; ic < 4; ic++)
                        #pragma unroll
                        for (int iq = 0; iq < 4; iq++) {
                            float2 f = unpack2(oacc2[ic][iq]);
                            sr[(cg + 16*ic)*QT + (qg + 8*iq)] += f.x + f.y;
                        }
                }
                __syncthreads();
            }
            // write buffer tile
            for (int i = tid; i < 64*QT; i += 256) {
                int c = i >> 5, q = i & 31;
                outg[(size_t)c*HW + q0 + q] = sr[i];
            }
            __syncthreads();
        }
        __syncthreads();
    }
}

// ---------------------------------------------------------------------------
// Kernel 3: direct 3x3 conv with packed f32x2 math.
// Tile: 64 out-ch x (64x x 4y). warp = o-group, lane = x-pair. Thread: 8o x 4py x 2x.
// Weights staged pre-duplicated (w,w) in smem -> LDS.64 gives packed operand.
// ---------------------------------------------------------------------------
#define SIN_FLOATS (16*6*68)                 // 6528
#define SW2_FLOATS (16*64*10*2)              // 20480
#define CONV_SMEM ((SIN_FLOATS + SW2_FLOATS) * 4)   // 108032 bytes

template<int CIN, bool RELU>
__global__ __launch_bounds__(256, 2)
void kconv(const float* __restrict__ in1, const float* __restrict__ in2,
           const float* __restrict__ Wt, float* __restrict__ out) {
    extern __shared__ float csm[];
    float* sin_ = csm;                       // [16][6][68]
    u64*   swp  = (u64*)(csm + SIN_FLOATS);  // [16][64][10] duplicated pairs

    int tid  = threadIdx.x;
    int lane = tid & 31, warp = tid >> 5;
    int x0 = blockIdx.x * 64;
    int y0 = blockIdx.y * 4;
    int b  = blockIdx.z;

    u64 acc[8][4];
    #pragma unroll
    for (int i = 0; i < 8; i++)
        #pragma unroll
        for (int j = 0; j < 4; j++) acc[i][j] = 0ull;

    for (int cb = 0; cb < CIN; cb += 16) {
        // stage input tile: rows y0-1..y0+4, cols x0-1..x0+64 (xi 0..65, pad 68)
        for (int i = tid; i < SIN_FLOATS; i += 256) {
            int ci  = i / 408;
            int rem = i % 408;
            int ry  = rem / 68;
            int xi  = rem % 68;
            int gy = y0 + ry - 1;
            int gx = x0 + xi - 1;
            float v = 0.f;
            if (xi < 66 && gy >= 0 && gy < HH && gx >= 0 && gx < WW) {
                int cglob = cb + ci;
                const float* src;
                if (CIN == 128 && cglob >= 64)
                    src = in2 + (size_t)b*CHW + (size_t)(cglob - 64)*HW;
                else
                    src = in1 + (size_t)b*CHW + (size_t)cglob*HW;
                v = src[gy*WW + gx];
            }
            sin_[i] = v;
        }
        // stage duplicated weights
        for (int i = tid; i < 16*64*9; i += 256) {
            int ci  = i / 576;
            int rem = i % 576;
            int o   = rem / 9;
            int t   = rem % 9;
            float w = Wt[(size_t)o*(CIN*9) + (size_t)(cb + ci)*9 + t];
            ((float2*)swp)[(ci*64 + o)*10 + t] = make_float2(w, w);
        }
        __syncthreads();

        #pragma unroll 1
        for (int ci = 0; ci < 16; ci++) {
            // build x-pair operands: pair (gx, gx+1) at tap dx needs xi = 2*lane+dx .. +1
            u64 v2[6][3];
            #pragma unroll
            for (int ry = 0; ry < 6; ry++) {
                float w4[4];
                #pragma unroll
                for (int k = 0; k < 4; k++)
                    w4[k] = sin_[ci*408 + ry*68 + 2*lane + k];
                #pragma unroll
                for (int dx = 0; dx < 3; dx++)
                    v2[ry][dx] = pack2(w4[dx], w4[dx+1]);
            }
            #pragma unroll 1
            for (int o8 = 0; o8 < 8; o8++) {
                const u64* wp = swp + (ci*64 + warp*8 + o8)*10;
                u64 w[9];
                #pragma unroll
                for (int t = 0; t < 9; t++) w[t] = wp[t];
                #pragma unroll
                for (int py = 0; py < 4; py++)
                    #pragma unroll
                    for (int ky = 0; ky < 3; ky++)
                        #pragma unroll
                        for (int dx = 0; dx < 3; dx++)
                            fma2(acc[o8][py], w[ky*3 + dx], v2[py + ky][dx]);
            }
        }
        __syncthreads();
    }

    #pragma unroll
    for (int o8 = 0; o8 < 8; o8++) {
        int o = warp*8 + o8;
        float* dst = out + (size_t)b*CHW + (size_t)o*HW + (size_t)y0*WW + x0 + 2*lane;
        #pragma unroll
        for (int py = 0; py < 4; py++) {
            float2 f = unpack2(acc[o8][py]);
            if (RELU) { f.x = fmaxf(f.x, 0.f); f.y = fmaxf(f.y, 0.f); }
            *(float2*)(dst + (size_t)py*WW) = f;
        }
    }
}

// ---------------------------------------------------------------------------
extern "C" void kernel_launch(void* const* d_in, const int* in_sizes, int n_in,
                              void* d_out, int out_size) {
    const float* u   = (const float*)d_in[0];
    const float* d   = (const float*)d_in[1];
    const float* Wu1 = (const float*)d_in[2];
    const float* Wu2 = (const float*)d_in[3];
    const float* Wd1 = (const float*)d_in[4];
    const float* Wd2 = (const float*)d_in[5];
    const float* W1a = (const float*)d_in[6];
    const float* W1b = (const float*)d_in[7];
    const float* W2a = (const float*)d_in[8];
    const float* W2b = (const float*)d_in[9];
    float* out = (float*)d_out;

    cudaFuncSetAttribute(kattn, cudaFuncAttributeMaxDynamicSharedMemorySize, ATTN_SMEM);
    cudaFuncSetAttribute(kconv<128, true>,  cudaFuncAttributeMaxDynamicSharedMemorySize, CONV_SMEM);
    cudaFuncSetAttribute(kconv<64, false>,  cudaFuncAttributeMaxDynamicSharedMemorySize, CONV_SMEM);

    float *pbuf0, *pbuf1, *pt0, *pt1;
    cudaGetSymbolAddress((void**)&pbuf0, g_buf);
    pbuf1 = pbuf0 + TENSOR_ELEMS;
    cudaGetSymbolAddress((void**)&pt0, g_t);
    pt1 = pt0 + TENSOR_ELEMS;

    // 1. fold 1x1 projections into 64x64 bilinear matrices
    kcomputeM<<<1, 256>>>(Wu1, Wd2, 0);   // M_ud
    kcomputeM<<<1, 256>>>(Wd1, Wu2, 1);   // M_du

    // 2. fused cross attention (both directions) -> g_buf
    kattn<<<BB*HH, 256, ATTN_SMEM>>>(u, d);

    // 3. conv1 + relu on concat(stream, buffer)
    dim3 grid(WW/64, HH/4, BB);
    kconv<128, true><<<grid, 256, CONV_SMEM>>>(u, pbuf0, W1a, pt0);
    kconv<128, true><<<grid, 256, CONV_SMEM>>>(d, pbuf1, W2a, pt1);

    // 4. conv2 -> outputs
    kconv<64, false><<<grid, 256, CONV_SMEM>>>(pt0, nullptr, W1b, out);
    kconv<64, false><<<grid, 256, CONV_SMEM>>>(pt1, nullptr, W2b, out + TENSOR_ELEMS);
}

// round 3
// speedup vs baseline: 1.9168x; 1.9168x over previous
#include <cuda_runtime.h>
#include <cstddef>
#include <cstdint>

#define HH 320
#define WW 320
#define CC 64
#define BB 2
#define HW (HH*WW)              // 102400
#define CHW ((size_t)CC*HW)     // 6553600
#define TENSOR_ELEMS (BB*CHW)   // 13107200

#define QT 32
#define ROWP 324                // padded row stride (floats) for smem rows

// Scratch (static device arrays; no allocation allowed)
__device__ float g_M[2*CC*CC];           // M_ud, M_du (64x64 each)
__device__ float g_buf[2][TENSOR_ELEMS]; // buffer_d, buffer_u
__device__ float g_t[2][TENSOR_ELEMS];   // relu(conv1) intermediates

__device__ __forceinline__ uint32_t f2tf32(float f) {
    uint32_t r; asm("cvt.rna.tf32.f32 %0, %1;" : "=r"(r) : "f"(f)); return r;
}
__device__ __forceinline__ void mma_tf32(float4& d,
        uint32_t a0, uint32_t a1, uint32_t a2, uint32_t a3,
        uint32_t b0, uint32_t b1) {
    asm("mma.sync.aligned.m16n8k8.row.col.f32.tf32.tf32.f32 "
        "{%0,%1,%2,%3}, {%4,%5,%6,%7}, {%8,%9}, {%0,%1,%2,%3};"
        : "+f"(d.x), "+f"(d.y), "+f"(d.z), "+f"(d.w)
        : "r"(a0), "r"(a1), "r"(a2), "r"(a3), "r"(b0), "r"(b1));
}

// ---------------------------------------------------------------------------
// Kernel 1: M[a][b] = sum_c Wq[c][a] * Wk[c][b]   (64x64)
// ---------------------------------------------------------------------------
__global__ void kcomputeM(const float* __restrict__ Wq,
                          const float* __restrict__ Wk, int dir) {
    __shared__ float sq[64*64];
    __shared__ float sk[64*64];
    int t = threadIdx.x;
    for (int i = t; i < 4096; i += 256) { sq[i] = Wq[i]; sk[i] = Wk[i]; }
    __syncthreads();
    for (int i = t; i < 4096; i += 256) {
        int a = i >> 6, b = i & 63;
        float s = 0.f;
        #pragma unroll 16
        for (int c = 0; c < 64; c++) s += sq[c*64 + a] * sk[c*64 + b];
        g_M[dir*4096 + i] = s;
    }
}

// ---------------------------------------------------------------------------
// Kernel 2: fused axial attention (R1 version, known-good fp32 scalar)
// ---------------------------------------------------------------------------
#define ATTN_SMEM ((64*ROWP*2 + QT*ROWP + 2048 + 4096) * 4)

__global__ __launch_bounds__(256)
void kattn(const float* __restrict__ u, const float* __restrict__ d) {
    extern __shared__ float smem[];
    float* su = smem;
    float* sd = su + 64*ROWP;
    float* sS = sd + 64*ROWP;
    float* sr = sS + QT*ROWP;
    float* sM = sr + 2048;

    int tid  = threadIdx.x;
    int lane = tid & 31, warp = tid >> 5;
    int b = blockIdx.x / HH, h = blockIdx.x % HH;
    const float* ubase = u + (size_t)b*CHW + (size_t)h*WW;
    const float* dbase = d + (size_t)b*CHW + (size_t)h*WW;

    for (int i = tid; i < 64*WW; i += 256) {
        int c = i / WW, w = i % WW;
        su[c*ROWP + w] = ubase[(size_t)c*HW + w];
        sd[c*ROWP + w] = dbase[(size_t)c*HW + w];
    }
    __syncthreads();

    for (int dir = 0; dir < 2; dir++) {
        const float* Mg = g_M + dir*4096;
        for (int i = tid; i < 4096; i += 256) sM[i] = Mg[i];
        float* sQ = (dir == 0) ? su : sd;
        float* sV = (dir == 0) ? sd : su;
        float* outg = g_buf[dir] + (size_t)b*CHW + (size_t)h*WW;
        __syncthreads();

        for (int q0 = 0; q0 < WW; q0 += QT) {
            for (int i = tid; i < 64*QT; i += 256) {
                int bb = i >> 5, q = i & 31;
                float s = 0.f;
                #pragma unroll 8
                for (int a = 0; a < 64; a++)
                    s += sQ[a*ROWP + q0 + q] * sM[a*64 + bb];
                sr[i] = s;
            }
            __syncthreads();

            float acc[4][10];
            #pragma unroll
            for (int i = 0; i < 4; i++)
                #pragma unroll
                for (int j = 0; j < 10; j++) acc[i][j] = 0.f;
            for (int bb = 0; bb < 64; bb++) {
                float rv[4];
                #pragma unroll
                for (int i = 0; i < 4; i++) rv[i] = sr[bb*QT + warp*4 + i];
                #pragma unroll
                for (int j = 0; j < 10; j++) {
                    float dv = sV[bb*ROWP + lane + 32*j];
                    #pragma unroll
                    for (int i = 0; i < 4; i++) acc[i][j] += rv[i]*dv;
                }
            }
            #pragma unroll
            for (int i = 0; i < 4; i++) {
                float m = acc[i][0];
                #pragma unroll
                for (int j = 1; j < 10; j++) m = fmaxf(m, acc[i][j]);
                #pragma unroll
                for (int o = 16; o > 0; o >>= 1) m = fmaxf(m, __shfl_xor_sync(~0u, m, o));
                float s = 0.f;
                #pragma unroll
                for (int j = 0; j < 10; j++) { acc[i][j] = __expf(acc[i][j] - m); s += acc[i][j]; }
                #pragma unroll
                for (int o = 16; o > 0; o >>= 1) s += __shfl_xor_sync(~0u, s, o);
                float inv = 1.f / s;
                #pragma unroll
                for (int j = 0; j < 10; j++)
                    sS[(warp*4 + i)*ROWP + lane + 32*j] = acc[i][j]*inv;
            }
            __syncthreads();

            {
                int half = tid >> 7;
                int t2 = tid & 127;
                int qg = t2 & 7;
                int cg = t2 >> 3;
                float oacc[4][4];
                #pragma unroll
                for (int ic = 0; ic < 4; ic++)
                    #pragma unroll
                    for (int iq = 0; iq < 4; iq++) oacc[ic][iq] = 0.f;
                int vbeg = half*160;
                for (int v = vbeg; v < vbeg + 160; v += 4) {
                    float4 pv[4], vv[4];
                    #pragma unroll
                    for (int iq = 0; iq < 4; iq++)
                        pv[iq] = *(const float4*)&sS[(qg + 8*iq)*ROWP + v];
                    #pragma unroll
                    for (int ic = 0; ic < 4; ic++)
                        vv[ic] = *(const float4*)&sV[(cg + 16*ic)*ROWP + v];
                    #pragma unroll
                    for (int ic = 0; ic < 4; ic++)
                        #pragma unroll
                        for (int iq = 0; iq < 4; iq++)
                            oacc[ic][iq] += vv[ic].x*pv[iq].x + vv[ic].y*pv[iq].y
                                          + vv[ic].z*pv[iq].z + vv[ic].w*pv[iq].w;
                }
                if (half == 0) {
                    #pragma unroll
                    for (int ic = 0; ic < 4; ic++)
                        #pragma unroll
                        for (int iq = 0; iq < 4; iq++)
                            sr[(cg + 16*ic)*QT + (qg + 8*iq)] = oacc[ic][iq];
                }
                __syncthreads();
                if (half == 1) {
                    #pragma unroll
                    for (int ic = 0; ic < 4; ic++)
                        #pragma unroll
                        for (int iq = 0; iq < 4; iq++)
                            sr[(cg + 16*ic)*QT + (qg + 8*iq)] += oacc[ic][iq];
                }
                __syncthreads();
            }
            for (int i = tid; i < 64*QT; i += 256) {
                int c = i >> 5, q = i & 31;
                outg[(size_t)c*HW + q0 + q] = sr[i];
            }
            __syncthreads();
        }
        __syncthreads();
    }
}

// ---------------------------------------------------------------------------
// Kernel 3: tf32 implicit-GEMM 3x3 conv via mma.sync.m16n8k8.
// Block: 64 o x (64x * 4y). Warp w: o-half = w&1 (32 o), row = w>>2... see below.
// Channel-pair permute [0,4,1,5,2,6,3,7] => A/B fragments are single LDS.64s.
// ---------------------------------------------------------------------------
#define SIN_U32 (6*68*8)        // 3264  : sin[row][x][perm(c)]
#define SW_U32  (9*64*8)        // 4608  : sw[tap][o][perm(c)]
#define CONV_SMEM ((SIN_U32 + SW_U32) * 4)   // 31488 bytes

template<int CIN, bool RELU>
__global__ __launch_bounds__(256, 2)
void kconv(const float* __restrict__ in1, const float* __restrict__ in2,
           const float* __restrict__ Wt, float* __restrict__ out) {
    extern __shared__ uint32_t csm[];
    uint32_t* sin_ = csm;            // [6][68][8]
    uint32_t* sw_  = csm + SIN_U32;  // [9][64][8]

    int tid  = threadIdx.x;
    int lane = tid & 31, warp = tid >> 5;
    int x0 = blockIdx.x * 64;
    int y0 = blockIdx.y * 4;
    int b  = blockIdx.z;

    int warp_o = warp & 1;      // 0/1 -> o base 0/32
    int warp_y = warp >> 1;     // 0..3 -> output row within tile

    int lq = lane >> 2;         // 0..7
    int lr = lane & 3;          // 0..3

    float4 acc[2][8];
    #pragma unroll
    for (int mt = 0; mt < 2; mt++)
        #pragma unroll
        for (int nt = 0; nt < 8; nt++) acc[mt][nt] = make_float4(0.f,0.f,0.f,0.f);

    for (int cb = 0; cb < CIN; cb += 8) {
        __syncthreads();
        // --- stage input chunk: 8 ch, rows y0-1..y0+4, x x0-1..x0+64 ---
        for (int i = tid; i < SIN_U32; i += 256) {
            int c   = i / 408;          // 6*68
            int rem = i % 408;
            int ry  = rem / 68;
            int x   = rem % 68;
            int gy = y0 + ry - 1;
            int gx = x0 + x - 1;
            float v = 0.f;
            if (x < 66 && gy >= 0 && gy < HH && gx >= 0 && gx < WW) {
                int cglob = cb + c;
                const float* src;
                if (CIN == 128 && cglob >= 64)
                    src = in2 + (size_t)b*CHW + (size_t)(cglob - 64)*HW;
                else
                    src = in1 + (size_t)b*CHW + (size_t)cglob*HW;
                v = src[gy*WW + gx];
            }
            int perm = (c & 3)*2 + (c >> 2);
            sin_[(ry*68 + x)*8 + perm] = f2tf32(v);
        }
        // --- stage weights chunk: sw[t][o][perm(c)] ---
        for (int i = tid; i < SW_U32; i += 256) {
            int o   = i / 72;
            int rem = i % 72;
            int c   = rem / 9;
            int t   = rem % 9;
            float w = Wt[(size_t)o*(CIN*9) + (size_t)(cb + c)*9 + t];
            int perm = (c & 3)*2 + (c >> 2);
            sw_[(t*64 + o)*8 + perm] = f2tf32(w);
        }
        __syncthreads();

        #pragma unroll
        for (int t = 0; t < 9; t++) {
            int ky = t / 3, kx = t % 3;
            int row = warp_y + ky;
            // A fragments for both m-tiles (o and o+8), via LDS.64 pairs
            uint32_t a[2][4];
            #pragma unroll
            for (int mt = 0; mt < 2; mt++) {
                int o_lo = warp_o*32 + mt*16 + lq;
                uint2 f0 = *(const uint2*)&sw_[(t*64 + o_lo)*8 + lr*2];
                uint2 f1 = *(const uint2*)&sw_[(t*64 + o_lo + 8)*8 + lr*2];
                a[mt][0] = f0.x; a[mt][1] = f1.x; a[mt][2] = f0.y; a[mt][3] = f1.y;
            }
            int pixbase = (row*68 + lq + kx)*8 + lr*2;
            #pragma unroll
            for (int nt = 0; nt < 8; nt++) {
                uint2 bfr = *(const uint2*)&sin_[pixbase + nt*64];
                mma_tf32(acc[0][nt], a[0][0], a[0][1], a[0][2], a[0][3], bfr.x, bfr.y);
                mma_tf32(acc[1][nt], a[1][0], a[1][1], a[1][2], a[1][3], bfr.x, bfr.y);
            }
        }
    }

    // --- writeback: d0,d1 -> (o, y, x..x+1); d2,d3 -> o+8 ---
    int y = y0 + warp_y;
    #pragma unroll
    for (int mt = 0; mt < 2; mt++) {
        int o_lo = warp_o*32 + mt*16 + lq;
        #pragma unroll
        for (int nt = 0; nt < 8; nt++) {
            int x = x0 + nt*8 + 2*lr;
            float4 v = acc[mt][nt];
            if (RELU) {
                v.x = fmaxf(v.x, 0.f); v.y = fmaxf(v.y, 0.f);
                v.z = fmaxf(v.z, 0.f); v.w = fmaxf(v.w, 0.f);
            }
            float* p0 = out + (size_t)b*CHW + (size_t)o_lo*HW + (size_t)y*WW + x;
            *(float2*)p0 = make_float2(v.x, v.y);
            float* p1 = p0 + (size_t)8*HW;
            *(float2*)p1 = make_float2(v.z, v.w);
        }
    }
}

// ---------------------------------------------------------------------------
extern "C" void kernel_launch(void* const* d_in, const int* in_sizes, int n_in,
                              void* d_out, int out_size) {
    const float* u   = (const float*)d_in[0];
    const float* d   = (const float*)d_in[1];
    const float* Wu1 = (const float*)d_in[2];
    const float* Wu2 = (const float*)d_in[3];
    const float* Wd1 = (const float*)d_in[4];
    const float* Wd2 = (const float*)d_in[5];
    const float* W1a = (const float*)d_in[6];
    const float* W1b = (const float*)d_in[7];
    const float* W2a = (const float*)d_in[8];
    const float* W2b = (const float*)d_in[9];
    float* out = (float*)d_out;

    cudaFuncSetAttribute(kattn, cudaFuncAttributeMaxDynamicSharedMemorySize, ATTN_SMEM);
    cudaFuncSetAttribute(kconv<128, true>,  cudaFuncAttributeMaxDynamicSharedMemorySize, CONV_SMEM);
    cudaFuncSetAttribute(kconv<64, false>,  cudaFuncAttributeMaxDynamicSharedMemorySize, CONV_SMEM);

    float *pbuf0, *pbuf1, *pt0, *pt1;
    cudaGetSymbolAddress((void**)&pbuf0, g_buf);
    pbuf1 = pbuf0 + TENSOR_ELEMS;
    cudaGetSymbolAddress((void**)&pt0, g_t);
    pt1 = pt0 + TENSOR_ELEMS;

    // 1. fold 1x1 projections into 64x64 bilinear matrices
    kcomputeM<<<1, 256>>>(Wu1, Wd2, 0);   // M_ud
    kcomputeM<<<1, 256>>>(Wd1, Wu2, 1);   // M_du

    // 2. fused cross attention (both directions) -> g_buf
    kattn<<<BB*HH, 256, ATTN_SMEM>>>(u, d);

    // 3. conv1 + relu on concat(stream, buffer)
    dim3 grid(WW/64, HH/4, BB);
    kconv<128, true><<<grid, 256, CONV_SMEM>>>(u, pbuf0, W1a, pt0);
    kconv<128, true><<<grid, 256, CONV_SMEM>>>(d, pbuf1, W2a, pt1);

    // 4. conv2 -> outputs
    kconv<64, false><<<grid, 256, CONV_SMEM>>>(pt0, nullptr, W1b, out);
    kconv<64, false><<<grid, 256, CONV_SMEM>>>(pt1, nullptr, W2b, out + TENSOR_ELEMS);
}

// round 4
// speedup vs baseline: 2.4723x; 1.2898x over previous
#include <cuda_runtime.h>
#include <cstddef>
#include <cstdint>

#define HH 320
#define WW 320
#define CC 64
#define BB 2
#define HW (HH*WW)              // 102400
#define CHW ((size_t)CC*HW)     // 6553600
#define TENSOR_ELEMS (BB*CHW)   // 13107200

#define QT 32
#define ROWP 324                // padded row stride (floats) for attn smem rows

// Scratch (static device arrays; no allocation allowed)
__device__ float    g_M[2*CC*CC];            // M_ud, M_du
__device__ uint32_t g_buf[2][TENSOR_ELEMS];  // buffer_d, buffer_u (tf32 bits)
__device__ uint32_t g_t[2][TENSOR_ELEMS];    // relu(conv1) intermediates (tf32 bits)
__device__ uint32_t g_utf[TENSOR_ELEMS];     // tf32(u)
__device__ uint32_t g_dtf[TENSOR_ELEMS];     // tf32(d)
// pre-permuted tf32 weights: [chunk][tap][o][18]
__device__ uint32_t g_wp1a[8*9*64*18];
__device__ uint32_t g_wp2a[8*9*64*18];
__device__ uint32_t g_wp1b[4*9*64*18];
__device__ uint32_t g_wp2b[4*9*64*18];

__device__ __forceinline__ uint32_t f2tf32(float f) {
    uint32_t r; asm("cvt.rna.tf32.f32 %0, %1;" : "=r"(r) : "f"(f)); return r;
}
__device__ __forceinline__ void mma_tf32(float4& d,
        uint32_t a0, uint32_t a1, uint32_t a2, uint32_t a3,
        uint32_t b0, uint32_t b1) {
    asm("mma.sync.aligned.m16n8k8.row.col.f32.tf32.tf32.f32 "
        "{%0,%1,%2,%3}, {%4,%5,%6,%7}, {%8,%9}, {%0,%1,%2,%3};"
        : "+f"(d.x), "+f"(d.y), "+f"(d.z), "+f"(d.w)
        : "r"(a0), "r"(a1), "r"(a2), "r"(a3), "r"(b0), "r"(b1));
}
__device__ __forceinline__ void cp16(uint32_t saddr, const void* gaddr, uint32_t sz) {
    asm volatile("cp.async.cg.shared.global [%0], [%1], 16, %2;"
                 :: "r"(saddr), "l"(gaddr), "r"(sz));
}
__device__ __forceinline__ void cpwait() {
    asm volatile("cp.async.commit_group;\n\tcp.async.wait_group 0;" ::: "memory");
}

// ---------------------------------------------------------------------------
// prep: convert u,d to tf32 bit arrays
// ---------------------------------------------------------------------------
__global__ void kprepin(const float* __restrict__ u, const float* __restrict__ d) {
    for (size_t i = (size_t)blockIdx.x*256 + threadIdx.x; i < TENSOR_ELEMS;
         i += (size_t)gridDim.x*256) {
        g_utf[i] = f2tf32(u[i]);
        g_dtf[i] = f2tf32(d[i]);
    }
}

// ---------------------------------------------------------------------------
// prep: permute+convert weights into [chunk][t][o][18] (pairs at s*8+2*lr)
// ---------------------------------------------------------------------------
__global__ void kprepw(const float* __restrict__ W, uint32_t* __restrict__ dst, int cin) {
    int total = (cin/16)*9*64*18;
    for (int i = blockIdx.x*256 + threadIdx.x; i < total; i += gridDim.x*256) {
        int w    = i % 18;
        int rest = i / 18;
        int o    = rest % 64;
        int rest2= rest / 64;
        int t    = rest2 % 9;
        int chunk= rest2 / 9;
        uint32_t v = 0;
        if (w < 16) {
            int s = w >> 3, p = w & 7;
            int c = (p >> 1) + ((p & 1) << 2);
            int cinidx = chunk*16 + s*8 + c;
            v = f2tf32(W[(size_t)o*(cin*9) + (size_t)cinidx*9 + t]);
        }
        dst[i] = v;
    }
}

// ---------------------------------------------------------------------------
// Kernel 1: M[a][b] = sum_c Wq[c][a] * Wk[c][b]   (64x64)
// ---------------------------------------------------------------------------
__global__ void kcomputeM(const float* __restrict__ Wq,
                          const float* __restrict__ Wk, int dir) {
    __shared__ float sq[64*64];
    __shared__ float sk[64*64];
    int t = threadIdx.x;
    for (int i = t; i < 4096; i += 256) { sq[i] = Wq[i]; sk[i] = Wk[i]; }
    __syncthreads();
    for (int i = t; i < 4096; i += 256) {
        int a = i >> 6, b = i & 63;
        float s = 0.f;
        #pragma unroll 16
        for (int c = 0; c < 64; c++) s += sq[c*64 + a] * sk[c*64 + b];
        g_M[dir*4096 + i] = s;
    }
}

// ---------------------------------------------------------------------------
// Kernel 2: fused axial attention (fp32 scalar, writes tf32 buffers)
// ---------------------------------------------------------------------------
#define ATTN_SMEM ((64*ROWP*2 + QT*ROWP + 2048 + 4096) * 4)

__global__ __launch_bounds__(256)
void kattn(const float* __restrict__ u, const float* __restrict__ d) {
    extern __shared__ float smem[];
    float* su = smem;
    float* sd = su + 64*ROWP;
    float* sS = sd + 64*ROWP;
    float* sr = sS + QT*ROWP;
    float* sM = sr + 2048;

    int tid  = threadIdx.x;
    int lane = tid & 31, warp = tid >> 5;
    int b = blockIdx.x / HH, h = blockIdx.x % HH;
    const float* ubase = u + (size_t)b*CHW + (size_t)h*WW;
    const float* dbase = d + (size_t)b*CHW + (size_t)h*WW;

    for (int i = tid; i < 64*WW; i += 256) {
        int c = i / WW, w = i % WW;
        su[c*ROWP + w] = ubase[(size_t)c*HW + w];
        sd[c*ROWP + w] = dbase[(size_t)c*HW + w];
    }
    __syncthreads();

    for (int dir = 0; dir < 2; dir++) {
        const float* Mg = g_M + dir*4096;
        for (int i = tid; i < 4096; i += 256) sM[i] = Mg[i];
        float* sQ = (dir == 0) ? su : sd;
        float* sV = (dir == 0) ? sd : su;
        uint32_t* outg = g_buf[dir] + (size_t)b*CHW + (size_t)h*WW;
        __syncthreads();

        for (int q0 = 0; q0 < WW; q0 += QT) {
            for (int i = tid; i < 64*QT; i += 256) {
                int bb = i >> 5, q = i & 31;
                float s = 0.f;
                #pragma unroll 8
                for (int a = 0; a < 64; a++)
                    s += sQ[a*ROWP + q0 + q] * sM[a*64 + bb];
                sr[i] = s;
            }
            __syncthreads();

            float acc[4][10];
            #pragma unroll
            for (int i = 0; i < 4; i++)
                #pragma unroll
                for (int j = 0; j < 10; j++) acc[i][j] = 0.f;
            for (int bb = 0; bb < 64; bb++) {
                float rv[4];
                #pragma unroll
                for (int i = 0; i < 4; i++) rv[i] = sr[bb*QT + warp*4 + i];
                #pragma unroll
                for (int j = 0; j < 10; j++) {
                    float dv = sV[bb*ROWP + lane + 32*j];
                    #pragma unroll
                    for (int i = 0; i < 4; i++) acc[i][j] += rv[i]*dv;
                }
            }
            #pragma unroll
            for (int i = 0; i < 4; i++) {
                float m = acc[i][0];
                #pragma unroll
                for (int j = 1; j < 10; j++) m = fmaxf(m, acc[i][j]);
                #pragma unroll
                for (int o = 16; o > 0; o >>= 1) m = fmaxf(m, __shfl_xor_sync(~0u, m, o));
                float s = 0.f;
                #pragma unroll
                for (int j = 0; j < 10; j++) { acc[i][j] = __expf(acc[i][j] - m); s += acc[i][j]; }
                #pragma unroll
                for (int o = 16; o > 0; o >>= 1) s += __shfl_xor_sync(~0u, s, o);
                float inv = 1.f / s;
                #pragma unroll
                for (int j = 0; j < 10; j++)
                    sS[(warp*4 + i)*ROWP + lane + 32*j] = acc[i][j]*inv;
            }
            __syncthreads();

            {
                int half = tid >> 7;
                int t2 = tid & 127;
                int qg = t2 & 7;
                int cg = t2 >> 3;
                float oacc[4][4];
                #pragma unroll
                for (int ic = 0; ic < 4; ic++)
                    #pragma unroll
                    for (int iq = 0; iq < 4; iq++) oacc[ic][iq] = 0.f;
                int vbeg = half*160;
                for (int v = vbeg; v < vbeg + 160; v += 4) {
                    float4 pv[4], vv[4];
                    #pragma unroll
                    for (int iq = 0; iq < 4; iq++)
                        pv[iq] = *(const float4*)&sS[(qg + 8*iq)*ROWP + v];
                    #pragma unroll
                    for (int ic = 0; ic < 4; ic++)
                        vv[ic] = *(const float4*)&sV[(cg + 16*ic)*ROWP + v];
                    #pragma unroll
                    for (int ic = 0; ic < 4; ic++)
                        #pragma unroll
                        for (int iq = 0; iq < 4; iq++)
                            oacc[ic][iq] += vv[ic].x*pv[iq].x + vv[ic].y*pv[iq].y
                                          + vv[ic].z*pv[iq].z + vv[ic].w*pv[iq].w;
                }
                if (half == 0) {
                    #pragma unroll
                    for (int ic = 0; ic < 4; ic++)
                        #pragma unroll
                        for (int iq = 0; iq < 4; iq++)
                            sr[(cg + 16*ic)*QT + (qg + 8*iq)] = oacc[ic][iq];
                }
                __syncthreads();
                if (half == 1) {
                    #pragma unroll
                    for (int ic = 0; ic < 4; ic++)
                        #pragma unroll
                        for (int iq = 0; iq < 4; iq++)
                            sr[(cg + 16*ic)*QT + (qg + 8*iq)] += oacc[ic][iq];
                }
                __syncthreads();
            }
            for (int i = tid; i < 64*QT; i += 256) {
                int c = i >> 5, q = i & 31;
                outg[(size_t)c*HW + q0 + q] = f2tf32(sr[i]);
            }
            __syncthreads();
        }
        __syncthreads();
    }
}

// ---------------------------------------------------------------------------
// Kernel 3: tf32 implicit-GEMM 3x3 conv; all operands pre-converted tf32.
// Input smem: [c16][6 rows x 72 x] plane-stride 440 (conflict-free B LDS.32).
// Weight smem: [t][o][18] pairs (2-phase floor A LDS.64). Staging = cp.async.
// ---------------------------------------------------------------------------
#define SIN_U32 (16*440)     // 7040
#define SW_U32  (9*64*18)    // 10368
#define CONV_SMEM ((SIN_U32 + SW_U32)*4)   // 69632 bytes

template<int CIN, bool FUSE>   // FUSE: relu + tf32-bit output
__global__ __launch_bounds__(256, 2)
void kconv(const uint32_t* __restrict__ in1, const uint32_t* __restrict__ in2,
           const uint32_t* __restrict__ wp, void* __restrict__ outv) {
    extern __shared__ uint32_t csm[];
    uint32_t* sin_ = csm;            // [16][440]
    uint32_t* sw_  = csm + SIN_U32;  // [9][64][18]

    int tid  = threadIdx.x;
    int lane = tid & 31, warp = tid >> 5;
    int x0 = blockIdx.x * 64;
    int y0 = blockIdx.y * 4;
    int b  = blockIdx.z;
    size_t bCHW = (size_t)b*CHW;

    int warp_o = warp & 1;
    int warp_y = warp >> 1;
    int lq = lane >> 2;
    int lr = lane & 3;

    uint32_t s_in_base = (uint32_t)__cvta_generic_to_shared(sin_);
    uint32_t s_w_base  = (uint32_t)__cvta_generic_to_shared(sw_);

    float4 acc[2][8];
    #pragma unroll
    for (int mt = 0; mt < 2; mt++)
        #pragma unroll
        for (int nt = 0; nt < 8; nt++) acc[mt][nt] = make_float4(0.f,0.f,0.f,0.f);

    for (int cb = 0; cb < CIN/16; cb++) {
        // ---- stage input: 16 ch x 6 rows x 18 quads via cp.async ----
        for (int i = tid; i < 1728; i += 256) {
            int c   = i / 108;
            int rem = i % 108;
            int r   = rem / 18;
            int q   = rem % 18;
            int gy = y0 + r - 1;
            int gx = x0 - 4 + q*4;
            uint32_t ok = (gy >= 0 && gy < HH && gx >= 0 && gx < WW) ? 16u : 0u;
            int cg = cb*16 + c;
            const uint32_t* plane;
            if (CIN == 128 && cg >= 64) plane = in2 + bCHW + (size_t)(cg - 64)*HW;
            else                        plane = in1 + bCHW + (size_t)cg*HW;
            const uint32_t* gsrc = ok ? (plane + gy*WW + gx) : plane;
            cp16(s_in_base + (c*440 + r*72 + q*4)*4, gsrc, ok);
        }
        // ---- stage weights: pure 16B copies ----
        const uint32_t* wsrc = wp + cb*SW_U32;
        for (int i = tid; i < SW_U32/4; i += 256)
            cp16(s_w_base + i*16, wsrc + i*4, 16);
        cpwait();
        __syncthreads();

        // ---- MMA ----
        #pragma unroll
        for (int t = 0; t < 9; t++) {
            int ky = t/3, kx = t - ky*3;
            int row = warp_y + ky;
            int bbase = row*72 + kx + 3 + lq;
            #pragma unroll
            for (int s = 0; s < 2; s++) {
                int aoff = (t*64 + warp_o*32)*18 + s*8 + 2*lr;
                uint2 a00 = *(const uint2*)&sw_[aoff + lq*18];
                uint2 a01 = *(const uint2*)&sw_[aoff + (lq+8)*18];
                uint2 a10 = *(const uint2*)&sw_[aoff + (lq+16)*18];
                uint2 a11 = *(const uint2*)&sw_[aoff + (lq+24)*18];
                int p0 = (s*8 + lr)*440 + bbase;
                int p1 = p0 + 4*440;
                #pragma unroll
                for (int nt = 0; nt < 8; nt++) {
                    uint32_t b0 = sin_[p0 + 8*nt];
                    uint32_t b1 = sin_[p1 + 8*nt];
                    mma_tf32(acc[0][nt], a00.x, a01.x, a00.y, a01.y, b0, b1);
                    mma_tf32(acc[1][nt], a10.x, a11.x, a10.y, a11.y, b0, b1);
                }
            }
        }
        __syncthreads();
    }

    // ---- writeback ----
    int y = y0 + warp_y;
    #pragma unroll
    for (int mt = 0; mt < 2; mt++) {
        int o_lo = warp_o*32 + mt*16 + lq;
        #pragma unroll
        for (int nt = 0; nt < 8; nt++) {
            int x = x0 + nt*8 + 2*lr;
            float4 v = acc[mt][nt];
            size_t off = bCHW + (size_t)o_lo*HW + (size_t)y*WW + x;
            if (FUSE) {
                uint32_t* outp = (uint32_t*)outv;
                uint2 r0 = make_uint2(f2tf32(fmaxf(v.x, 0.f)), f2tf32(fmaxf(v.y, 0.f)));
                uint2 r1 = make_uint2(f2tf32(fmaxf(v.z, 0.f)), f2tf32(fmaxf(v.w, 0.f)));
                *(uint2*)(outp + off)            = r0;
                *(uint2*)(outp + off + 8*HW)     = r1;
            } else {
                float* outp = (float*)outv;
                *(float2*)(outp + off)           = make_float2(v.x, v.y);
                *(float2*)(outp + off + 8*HW)    = make_float2(v.z, v.w);
            }
        }
    }
}

// ---------------------------------------------------------------------------
extern "C" void kernel_launch(void* const* d_in, const int* in_sizes, int n_in,
                              void* d_out, int out_size) {
    const float* u   = (const float*)d_in[0];
    const float* d   = (const float*)d_in[1];
    const float* Wu1 = (const float*)d_in[2];
    const float* Wu2 = (const float*)d_in[3];
    const float* Wd1 = (const float*)d_in[4];
    const float* Wd2 = (const float*)d_in[5];
    const float* W1a = (const float*)d_in[6];
    const float* W1b = (const float*)d_in[7];
    const float* W2a = (const float*)d_in[8];
    const float* W2b = (const float*)d_in[9];
    float* out = (float*)d_out;

    cudaFuncSetAttribute(kattn, cudaFuncAttributeMaxDynamicSharedMemorySize, ATTN_SMEM);
    cudaFuncSetAttribute(kconv<128, true>,  cudaFuncAttributeMaxDynamicSharedMemorySize, CONV_SMEM);
    cudaFuncSetAttribute(kconv<64, false>,  cudaFuncAttributeMaxDynamicSharedMemorySize, CONV_SMEM);

    uint32_t *pbuf0, *pbuf1, *pt0, *pt1, *putf, *pdtf;
    uint32_t *pw1a, *pw2a, *pw1b, *pw2b;
    cudaGetSymbolAddress((void**)&pbuf0, g_buf);   pbuf1 = pbuf0 + TENSOR_ELEMS;
    cudaGetSymbolAddress((void**)&pt0,   g_t);     pt1   = pt0   + TENSOR_ELEMS;
    cudaGetSymbolAddress((void**)&putf,  g_utf);
    cudaGetSymbolAddress((void**)&pdtf,  g_dtf);
    cudaGetSymbolAddress((void**)&pw1a,  g_wp1a);
    cudaGetSymbolAddress((void**)&pw2a,  g_wp2a);
    cudaGetSymbolAddress((void**)&pw1b,  g_wp1b);
    cudaGetSymbolAddress((void**)&pw2b,  g_wp2b);

    // prep
    kprepin<<<2048, 256>>>(u, d);
    kprepw<<<(8*9*64*18 + 255)/256, 256>>>(W1a, pw1a, 128);
    kprepw<<<(8*9*64*18 + 255)/256, 256>>>(W2a, pw2a, 128);
    kprepw<<<(4*9*64*18 + 255)/256, 256>>>(W1b, pw1b, 64);
    kprepw<<<(4*9*64*18 + 255)/256, 256>>>(W2b, pw2b, 64);
    kcomputeM<<<1, 256>>>(Wu1, Wd2, 0);
    kcomputeM<<<1, 256>>>(Wd1, Wu2, 1);

    // attention -> tf32 buffers
    kattn<<<BB*HH, 256, ATTN_SMEM>>>(u, d);

    // conv1 + relu (tf32 out), then conv2 (fp32 out)
    dim3 grid(WW/64, HH/4, BB);
    kconv<128, true><<<grid, 256, CONV_SMEM>>>(putf, pbuf0, pw1a, pt0);
    kconv<128, true><<<grid, 256, CONV_SMEM>>>(pdtf, pbuf1, pw2a, pt1);
    kconv<64, false><<<grid, 256, CONV_SMEM>>>(pt0, pt0, pw1b, out);
    kconv<64, false><<<grid, 256, CONV_SMEM>>>(pt1, pt1, pw2b, out + TENSOR_ELEMS);
}

// round 5
// speedup vs baseline: 4.4019x; 1.7805x over previous
#include <cuda_runtime.h>
#include <cstddef>
#include <cstdint>

#define HH 320
#define WW 320
#define CC 64
#define BB 2
#define HW (HH*WW)              // 102400
#define CHW ((size_t)CC*HW)     // 6553600
#define TENSOR_ELEMS (BB*CHW)   // 13107200

// Scratch (static device arrays; no allocation allowed)
__device__ uint32_t g_Mt[2*CC*CC];           // tf32(M^T) per dir
__device__ uint32_t g_buf[2][TENSOR_ELEMS];  // buffer_d, buffer_u (tf32 bits)
__device__ uint32_t g_t[2][TENSOR_ELEMS];    // relu(conv1) intermediates (tf32 bits)
__device__ uint32_t g_utf[TENSOR_ELEMS];     // tf32(u)
__device__ uint32_t g_dtf[TENSOR_ELEMS];     // tf32(d)
// pre-permuted tf32 weights: [chunk][tap][o][18]
__device__ uint32_t g_wp1a[8*9*64*18];
__device__ uint32_t g_wp2a[8*9*64*18];
__device__ uint32_t g_wp1b[4*9*64*18];
__device__ uint32_t g_wp2b[4*9*64*18];

__device__ __forceinline__ uint32_t f2tf32(float f) {
    uint32_t r; asm("cvt.rna.tf32.f32 %0, %1;" : "=r"(r) : "f"(f)); return r;
}
__device__ __forceinline__ void mma_tf32(float4& d,
        uint32_t a0, uint32_t a1, uint32_t a2, uint32_t a3,
        uint32_t b0, uint32_t b1) {
    asm("mma.sync.aligned.m16n8k8.row.col.f32.tf32.tf32.f32 "
        "{%0,%1,%2,%3}, {%4,%5,%6,%7}, {%8,%9}, {%0,%1,%2,%3};"
        : "+f"(d.x), "+f"(d.y), "+f"(d.z), "+f"(d.w)
        : "r"(a0), "r"(a1), "r"(a2), "r"(a3), "r"(b0), "r"(b1));
}
__device__ __forceinline__ void cp16(uint32_t saddr, const void* gaddr, uint32_t sz) {
    asm volatile("cp.async.cg.shared.global [%0], [%1], 16, %2;"
                 :: "r"(saddr), "l"(gaddr), "r"(sz));
}
__device__ __forceinline__ void cpwait() {
    asm volatile("cp.async.commit_group;\n\tcp.async.wait_group 0;" ::: "memory");
}
__device__ __forceinline__ uint32_t fu(float f) { return __float_as_uint(f); }

// ---------------------------------------------------------------------------
// prep: convert u,d to tf32 bit arrays
// ---------------------------------------------------------------------------
__global__ void kprepin(const float* __restrict__ u, const float* __restrict__ d) {
    for (size_t i = (size_t)blockIdx.x*256 + threadIdx.x; i < TENSOR_ELEMS;
         i += (size_t)gridDim.x*256) {
        g_utf[i] = f2tf32(u[i]);
        g_dtf[i] = f2tf32(d[i]);
    }
}

// ---------------------------------------------------------------------------
// prep: permute+convert weights into [chunk][t][o][18]
// ---------------------------------------------------------------------------
__global__ void kprepw(const float* __restrict__ W, uint32_t* __restrict__ dst, int cin) {
    int total = (cin/16)*9*64*18;
    for (int i = blockIdx.x*256 + threadIdx.x; i < total; i += gridDim.x*256) {
        int w    = i % 18;
        int rest = i / 18;
        int o    = rest % 64;
        int rest2= rest / 64;
        int t    = rest2 % 9;
        int chunk= rest2 / 9;
        uint32_t v = 0;
        if (w < 16) {
            int s = w >> 3, p = w & 7;
            int c = (p >> 1) + ((p & 1) << 2);
            int cinidx = chunk*16 + s*8 + c;
            v = f2tf32(W[(size_t)o*(cin*9) + (size_t)cinidx*9 + t]);
        }
        dst[i] = v;
    }
}

// ---------------------------------------------------------------------------
// Kernel 1: Mt[dir][b][a] = tf32( sum_c Wq[c][a] * Wk[c][b] )
// ---------------------------------------------------------------------------
__global__ void kcomputeM(const float* __restrict__ Wq,
                          const float* __restrict__ Wk, int dir) {
    __shared__ float sq[64*64];
    __shared__ float sk[64*64];
    int t = threadIdx.x;
    for (int i = t; i < 4096; i += 256) { sq[i] = Wq[i]; sk[i] = Wk[i]; }
    __syncthreads();
    for (int i = t; i < 4096; i += 256) {
        int a = i >> 6, b = i & 63;
        float s = 0.f;
        #pragma unroll 16
        for (int c = 0; c < 64; c++) s += sq[c*64 + a] * sk[c*64 + b];
        g_Mt[dir*4096 + b*64 + a] = f2tf32(s);
    }
}

// ---------------------------------------------------------------------------
// Kernel 2: tensor-core axial attention. One block per (b,h), both dirs.
// smem: su[64][328], sd[64][328], sP[32][328], sR[64][36]
// ---------------------------------------------------------------------------
#define ATTN_SMEM ((64*328*2 + 32*328 + 64*36)*4)   // 219136 B

__global__ __launch_bounds__(256)
void kattn(int dummy) {
    extern __shared__ float smem[];
    float* su = smem;                 // 64*328
    float* sd = su + 64*328;
    float* sP = sd + 64*328;          // 32*328
    float* sR = sP + 32*328;          // 64*36

    int tid  = threadIdx.x;
    int lane = tid & 31, warp = tid >> 5;
    int gid  = lane >> 2, tid4 = lane & 3;
    int b = blockIdx.x / HH, h = blockIdx.x % HH;
    const uint32_t* ub = g_utf + (size_t)b*CHW + (size_t)h*WW;
    const uint32_t* db = g_dtf + (size_t)b*CHW + (size_t)h*WW;

    // stage both streams' rows (tf32 bits, valid fp32 values)
    for (int i = tid; i < 64*80; i += 256) {
        int c = i / 80, q4 = (i % 80) * 4;
        uint4 vu = *(const uint4*)(ub + (size_t)c*HW + q4);
        uint4 vd = *(const uint4*)(db + (size_t)c*HW + q4);
        *(uint4*)&su[c*328 + q4] = vu;
        *(uint4*)&sd[c*328 + q4] = vd;
    }

    for (int dir = 0; dir < 2; dir++) {
        const float* sQ = dir ? sd : su;
        const float* sV = dir ? su : sd;
        uint32_t* outg = g_buf[dir] + (size_t)b*CHW + (size_t)h*WW;

        // Mt fragments for R GEMM (warp: bg = b-group of 16, qh = q-half)
        const uint32_t* Mt = g_Mt + dir*4096;
        int bg = warp & 3, qh = warp >> 2;
        uint32_t am[8][4];
        {
            int r = bg*16 + gid;
            #pragma unroll
            for (int k = 0; k < 8; k++) {
                int c0 = k*8 + tid4;
                am[k][0] = Mt[r*64 + c0];
                am[k][1] = Mt[(r+8)*64 + c0];
                am[k][2] = Mt[r*64 + c0 + 4];
                am[k][3] = Mt[(r+8)*64 + c0 + 4];
            }
        }

        for (int q0 = 0; q0 < WW; q0 += 32) {
            __syncthreads();    // sR free (prev attend), sP free (prev score)

            // ---- R[b][q] = sum_a Mt[b][a] Q[a][q]  (warp: 16b x 16q) ----
            float4 rc[2];
            rc[0] = make_float4(0.f,0.f,0.f,0.f);
            rc[1] = make_float4(0.f,0.f,0.f,0.f);
            #pragma unroll
            for (int k = 0; k < 8; k++) {
                #pragma unroll
                for (int nt = 0; nt < 2; nt++) {
                    int qq = q0 + qh*16 + nt*8 + gid;
                    uint32_t b0 = fu(sQ[(k*8 + tid4)*328 + qq]);
                    uint32_t b1 = fu(sQ[(k*8 + tid4 + 4)*328 + qq]);
                    mma_tf32(rc[nt], am[k][0], am[k][1], am[k][2], am[k][3], b0, b1);
                }
            }
            #pragma unroll
            for (int nt = 0; nt < 2; nt++) {
                int q = qh*16 + nt*8 + 2*tid4;
                int bb = bg*16 + gid;
                *(uint2*)&sR[bb*36 + q]     = make_uint2(f2tf32(rc[nt].x), f2tf32(rc[nt].y));
                *(uint2*)&sR[(bb+8)*36 + q] = make_uint2(f2tf32(rc[nt].z), f2tf32(rc[nt].w));
            }
            __syncthreads();

            // ---- S[q][v] = sum_b R[b][q] V[b][v]  (warp: 16q x 80v) ----
            {
                int qg = warp >> 2, vg = warp & 3;
                float4 sc[10];
                #pragma unroll
                for (int nt = 0; nt < 10; nt++) sc[nt] = make_float4(0.f,0.f,0.f,0.f);
                #pragma unroll
                for (int k = 0; k < 8; k++) {
                    uint32_t a0 = fu(sR[(k*8 + tid4)*36 + qg*16 + gid]);
                    uint32_t a1 = fu(sR[(k*8 + tid4)*36 + qg*16 + gid + 8]);
                    uint32_t a2 = fu(sR[(k*8 + tid4 + 4)*36 + qg*16 + gid]);
                    uint32_t a3 = fu(sR[(k*8 + tid4 + 4)*36 + qg*16 + gid + 8]);
                    #pragma unroll
                    for (int nt = 0; nt < 10; nt++) {
                        int vv = vg*80 + nt*8 + gid;
                        uint32_t b0 = fu(sV[(k*8 + tid4)*328 + vv]);
                        uint32_t b1 = fu(sV[(k*8 + tid4 + 4)*328 + vv]);
                        mma_tf32(sc[nt], a0, a1, a2, a3, b0, b1);
                    }
                }
                #pragma unroll
                for (int nt = 0; nt < 10; nt++) {
                    int q = qg*16 + gid, v = vg*80 + nt*8 + 2*tid4;
                    *(float2*)&sP[q*328 + v]     = make_float2(sc[nt].x, sc[nt].y);
                    *(float2*)&sP[(q+8)*328 + v] = make_float2(sc[nt].z, sc[nt].w);
                }
            }
            __syncthreads();

            // ---- softmax rows warp*4..+3 over 320 v; store tf32 P ----
            #pragma unroll
            for (int i = 0; i < 4; i++) {
                int row = warp*4 + i;
                float a[10];
                #pragma unroll
                for (int j = 0; j < 10; j++) a[j] = sP[row*328 + lane + 32*j];
                float m = a[0];
                #pragma unroll
                for (int j = 1; j < 10; j++) m = fmaxf(m, a[j]);
                #pragma unroll
                for (int o = 16; o > 0; o >>= 1) m = fmaxf(m, __shfl_xor_sync(~0u, m, o));
                float s = 0.f;
                #pragma unroll
                for (int j = 0; j < 10; j++) { a[j] = __expf(a[j] - m); s += a[j]; }
                #pragma unroll
                for (int o = 16; o > 0; o >>= 1) s += __shfl_xor_sync(~0u, s, o);
                float inv = 1.f / s;
                #pragma unroll
                for (int j = 0; j < 10; j++)
                    sP[row*328 + lane + 32*j] = __uint_as_float(f2tf32(a[j]*inv));
            }
            __syncthreads();

            // ---- out[c][q] = sum_v V[c][v] P[q][v]  (warp: 16c x 32q, K half) ----
            {
                int cg = warp & 3, kh = warp >> 2;
                float4 oc[4];
                #pragma unroll
                for (int nt = 0; nt < 4; nt++) oc[nt] = make_float4(0.f,0.f,0.f,0.f);
                #pragma unroll
                for (int k = 0; k < 20; k++) {
                    int kb = kh*160 + k*8;
                    uint32_t a0 = fu(sV[(cg*16 + gid)*328 + kb + tid4]);
                    uint32_t a1 = fu(sV[(cg*16 + gid + 8)*328 + kb + tid4]);
                    uint32_t a2 = fu(sV[(cg*16 + gid)*328 + kb + tid4 + 4]);
                    uint32_t a3 = fu(sV[(cg*16 + gid + 8)*328 + kb + tid4 + 4]);
                    #pragma unroll
                    for (int nt = 0; nt < 4; nt++) {
                        uint32_t b0 = fu(sP[(nt*8 + gid)*328 + kb + tid4]);
                        uint32_t b1 = fu(sP[(nt*8 + gid)*328 + kb + tid4 + 4]);
                        mma_tf32(oc[nt], a0, a1, a2, a3, b0, b1);
                    }
                }
                if (kh == 0) {
                    #pragma unroll
                    for (int nt = 0; nt < 4; nt++) {
                        int c = cg*16 + gid, q = nt*8 + 2*tid4;
                        *(float2*)&sR[c*36 + q]     = make_float2(oc[nt].x, oc[nt].y);
                        *(float2*)&sR[(c+8)*36 + q] = make_float2(oc[nt].z, oc[nt].w);
                    }
                }
                __syncthreads();
                if (kh == 1) {
                    #pragma unroll
                    for (int nt = 0; nt < 4; nt++) {
                        int c = cg*16 + gid, q = nt*8 + 2*tid4;
                        float2 r0 = *(const float2*)&sR[c*36 + q];
                        float2 r1 = *(const float2*)&sR[(c+8)*36 + q];
                        uint2 w0 = make_uint2(f2tf32(oc[nt].x + r0.x), f2tf32(oc[nt].y + r0.y));
                        uint2 w1 = make_uint2(f2tf32(oc[nt].z + r1.x), f2tf32(oc[nt].w + r1.y));
                        *(uint2*)(outg + (size_t)c*HW + q0 + q)     = w0;
                        *(uint2*)(outg + (size_t)(c+8)*HW + q0 + q) = w1;
                    }
                }
            }
        }
        __syncthreads();
    }
}

// ---------------------------------------------------------------------------
// Kernel 3: tf32 implicit-GEMM 3x3 conv (unchanged from R4).
// ---------------------------------------------------------------------------
#define SIN_U32 (16*440)     // 7040
#define SW_U32  (9*64*18)    // 10368
#define CONV_SMEM ((SIN_U32 + SW_U32)*4)   // 69632 bytes

template<int CIN, bool FUSE>
__global__ __launch_bounds__(256, 2)
void kconv(const uint32_t* __restrict__ in1, const uint32_t* __restrict__ in2,
           const uint32_t* __restrict__ wp, void* __restrict__ outv) {
    extern __shared__ uint32_t csm[];
    uint32_t* sin_ = csm;            // [16][440]
    uint32_t* sw_  = csm + SIN_U32;  // [9][64][18]

    int tid  = threadIdx.x;
    int lane = tid & 31, warp = tid >> 5;
    int x0 = blockIdx.x * 64;
    int y0 = blockIdx.y * 4;
    int b  = blockIdx.z;
    size_t bCHW = (size_t)b*CHW;

    int warp_o = warp & 1;
    int warp_y = warp >> 1;
    int lq = lane >> 2;
    int lr = lane & 3;

    uint32_t s_in_base = (uint32_t)__cvta_generic_to_shared(sin_);
    uint32_t s_w_base  = (uint32_t)__cvta_generic_to_shared(sw_);

    float4 acc[2][8];
    #pragma unroll
    for (int mt = 0; mt < 2; mt++)
        #pragma unroll
        for (int nt = 0; nt < 8; nt++) acc[mt][nt] = make_float4(0.f,0.f,0.f,0.f);

    for (int cb = 0; cb < CIN/16; cb++) {
        for (int i = tid; i < 1728; i += 256) {
            int c   = i / 108;
            int rem = i % 108;
            int r   = rem / 18;
            int q   = rem % 18;
            int gy = y0 + r - 1;
            int gx = x0 - 4 + q*4;
            uint32_t ok = (gy >= 0 && gy < HH && gx >= 0 && gx < WW) ? 16u : 0u;
            int cg = cb*16 + c;
            const uint32_t* plane;
            if (CIN == 128 && cg >= 64) plane = in2 + bCHW + (size_t)(cg - 64)*HW;
            else                        plane = in1 + bCHW + (size_t)cg*HW;
            const uint32_t* gsrc = ok ? (plane + gy*WW + gx) : plane;
            cp16(s_in_base + (c*440 + r*72 + q*4)*4, gsrc, ok);
        }
        const uint32_t* wsrc = wp + cb*SW_U32;
        for (int i = tid; i < SW_U32/4; i += 256)
            cp16(s_w_base + i*16, wsrc + i*4, 16);
        cpwait();
        __syncthreads();

        #pragma unroll
        for (int t = 0; t < 9; t++) {
            int ky = t/3, kx = t - ky*3;
            int row = warp_y + ky;
            int bbase = row*72 + kx + 3 + lq;
            #pragma unroll
            for (int s = 0; s < 2; s++) {
                int aoff = (t*64 + warp_o*32)*18 + s*8 + 2*lr;
                uint2 a00 = *(const uint2*)&sw_[aoff + lq*18];
                uint2 a01 = *(const uint2*)&sw_[aoff + (lq+8)*18];
                uint2 a10 = *(const uint2*)&sw_[aoff + (lq+16)*18];
                uint2 a11 = *(const uint2*)&sw_[aoff + (lq+24)*18];
                int p0 = (s*8 + lr)*440 + bbase;
                int p1 = p0 + 4*440;
                #pragma unroll
                for (int nt = 0; nt < 8; nt++) {
                    uint32_t b0 = sin_[p0 + 8*nt];
                    uint32_t b1 = sin_[p1 + 8*nt];
                    mma_tf32(acc[0][nt], a00.x, a01.x, a00.y, a01.y, b0, b1);
                    mma_tf32(acc[1][nt], a10.x, a11.x, a10.y, a11.y, b0, b1);
                }
            }
        }
        __syncthreads();
    }

    int y = y0 + warp_y;
    #pragma unroll
    for (int mt = 0; mt < 2; mt++) {
        int o_lo = warp_o*32 + mt*16 + lq;
        #pragma unroll
        for (int nt = 0; nt < 8; nt++) {
            int x = x0 + nt*8 + 2*lr;
            float4 v = acc[mt][nt];
            size_t off = bCHW + (size_t)o_lo*HW + (size_t)y*WW + x;
            if (FUSE) {
                uint32_t* outp = (uint32_t*)outv;
                uint2 r0 = make_uint2(f2tf32(fmaxf(v.x, 0.f)), f2tf32(fmaxf(v.y, 0.f)));
                uint2 r1 = make_uint2(f2tf32(fmaxf(v.z, 0.f)), f2tf32(fmaxf(v.w, 0.f)));
                *(uint2*)(outp + off)            = r0;
                *(uint2*)(outp + off + 8*HW)     = r1;
            } else {
                float* outp = (float*)outv;
                *(float2*)(outp + off)           = make_float2(v.x, v.y);
                *(float2*)(outp + off + 8*HW)    = make_float2(v.z, v.w);
            }
        }
    }
}

// ---------------------------------------------------------------------------
extern "C" void kernel_launch(void* const* d_in, const int* in_sizes, int n_in,
                              void* d_out, int out_size) {
    const float* u   = (const float*)d_in[0];
    const float* d   = (const float*)d_in[1];
    const float* Wu1 = (const float*)d_in[2];
    const float* Wu2 = (const float*)d_in[3];
    const float* Wd1 = (const float*)d_in[4];
    const float* Wd2 = (const float*)d_in[5];
    const float* W1a = (const float*)d_in[6];
    const float* W1b = (const float*)d_in[7];
    const float* W2a = (const float*)d_in[8];
    const float* W2b = (const float*)d_in[9];
    float* out = (float*)d_out;

    cudaFuncSetAttribute(kattn, cudaFuncAttributeMaxDynamicSharedMemorySize, ATTN_SMEM);
    cudaFuncSetAttribute(kconv<128, true>,  cudaFuncAttributeMaxDynamicSharedMemorySize, CONV_SMEM);
    cudaFuncSetAttribute(kconv<64, false>,  cudaFuncAttributeMaxDynamicSharedMemorySize, CONV_SMEM);

    uint32_t *pbuf0, *pbuf1, *pt0, *pt1, *putf, *pdtf;
    uint32_t *pw1a, *pw2a, *pw1b, *pw2b;
    cudaGetSymbolAddress((void**)&pbuf0, g_buf);   pbuf1 = pbuf0 + TENSOR_ELEMS;
    cudaGetSymbolAddress((void**)&pt0,   g_t);     pt1   = pt0   + TENSOR_ELEMS;
    cudaGetSymbolAddress((void**)&putf,  g_utf);
    cudaGetSymbolAddress((void**)&pdtf,  g_dtf);
    cudaGetSymbolAddress((void**)&pw1a,  g_wp1a);
    cudaGetSymbolAddress((void**)&pw2a,  g_wp2a);
    cudaGetSymbolAddress((void**)&pw1b,  g_wp1b);
    cudaGetSymbolAddress((void**)&pw2b,  g_wp2b);

    // prep
    kprepin<<<2048, 256>>>(u, d);
    kprepw<<<(8*9*64*18 + 255)/256, 256>>>(W1a, pw1a, 128);
    kprepw<<<(8*9*64*18 + 255)/256, 256>>>(W2a, pw2a, 128);
    kprepw<<<(4*9*64*18 + 255)/256, 256>>>(W1b, pw1b, 64);
    kprepw<<<(4*9*64*18 + 255)/256, 256>>>(W2b, pw2b, 64);
    kcomputeM<<<1, 256>>>(Wu1, Wd2, 0);
    kcomputeM<<<1, 256>>>(Wd1, Wu2, 1);

    // attention (tensor core) -> tf32 buffers
    kattn<<<BB*HH, 256, ATTN_SMEM>>>(0);

    // conv1 + relu (tf32 out), then conv2 (fp32 out)
    dim3 grid(WW/64, HH/4, BB);
    kconv<128, true><<<grid, 256, CONV_SMEM>>>(putf, pbuf0, pw1a, pt0);
    kconv<128, true><<<grid, 256, CONV_SMEM>>>(pdtf, pbuf1, pw2a, pt1);
    kconv<64, false><<<grid, 256, CONV_SMEM>>>(pt0, pt0, pw1b, out);
    kconv<64, false><<<grid, 256, CONV_SMEM>>>(pt1, pt1, pw2b, out + TENSOR_ELEMS);
}

// round 6
// speedup vs baseline: 4.5143x; 1.0255x over previous
#include <cuda_runtime.h>
#include <cstddef>
#include <cstdint>

#define HH 320
#define WW 320
#define CC 64
#define BB 2
#define HW (HH*WW)              // 102400
#define CHW ((size_t)CC*HW)     // 6553600
#define TENSOR_ELEMS (BB*CHW)   // 13107200

// Scratch (static device arrays; no allocation allowed)
__device__ uint32_t g_Mt[2*CC*CC];           // tf32(M^T) per dir
__device__ uint32_t g_buf[2][TENSOR_ELEMS];  // buffer_d, buffer_u (tf32 bits)
__device__ uint32_t g_t[2][TENSOR_ELEMS];    // relu(conv1) intermediates (tf32 bits)
__device__ uint32_t g_utf[TENSOR_ELEMS];     // tf32(u)
__device__ uint32_t g_dtf[TENSOR_ELEMS];     // tf32(d)
// pre-permuted tf32 weights: [chunk][tap][o][18]
__device__ uint32_t g_wp1a[8*9*64*18];
__device__ uint32_t g_wp2a[8*9*64*18];
__device__ uint32_t g_wp1b[4*9*64*18];
__device__ uint32_t g_wp2b[4*9*64*18];

__device__ __forceinline__ uint32_t f2tf32(float f) {
    uint32_t r; asm("cvt.rna.tf32.f32 %0, %1;" : "=r"(r) : "f"(f)); return r;
}
__device__ __forceinline__ void mma_tf32(float4& d,
        uint32_t a0, uint32_t a1, uint32_t a2, uint32_t a3,
        uint32_t b0, uint32_t b1) {
    asm("mma.sync.aligned.m16n8k8.row.col.f32.tf32.tf32.f32 "
        "{%0,%1,%2,%3}, {%4,%5,%6,%7}, {%8,%9}, {%0,%1,%2,%3};"
        : "+f"(d.x), "+f"(d.y), "+f"(d.z), "+f"(d.w)
        : "r"(a0), "r"(a1), "r"(a2), "r"(a3), "r"(b0), "r"(b1));
}
__device__ __forceinline__ void cp16(uint32_t saddr, const void* gaddr, uint32_t sz) {
    asm volatile("cp.async.cg.shared.global [%0], [%1], 16, %2;"
                 :: "r"(saddr), "l"(gaddr), "r"(sz));
}
__device__ __forceinline__ uint32_t fu(float f) { return __float_as_uint(f); }

// ---------------------------------------------------------------------------
// prep kernels
// ---------------------------------------------------------------------------
__global__ void kprepin(const float* __restrict__ u, const float* __restrict__ d) {
    for (size_t i = (size_t)blockIdx.x*256 + threadIdx.x; i < TENSOR_ELEMS;
         i += (size_t)gridDim.x*256) {
        g_utf[i] = f2tf32(u[i]);
        g_dtf[i] = f2tf32(d[i]);
    }
}

__global__ void kprepw(const float* __restrict__ W, uint32_t* __restrict__ dst, int cin) {
    int total = (cin/16)*9*64*18;
    for (int i = blockIdx.x*256 + threadIdx.x; i < total; i += gridDim.x*256) {
        int w    = i % 18;
        int rest = i / 18;
        int o    = rest % 64;
        int rest2= rest / 64;
        int t    = rest2 % 9;
        int chunk= rest2 / 9;
        uint32_t v = 0;
        if (w < 16) {
            int s = w >> 3, p = w & 7;
            int c = (p >> 1) + ((p & 1) << 2);
            int cinidx = chunk*16 + s*8 + c;
            v = f2tf32(W[(size_t)o*(cin*9) + (size_t)cinidx*9 + t]);
        }
        dst[i] = v;
    }
}

__global__ void kcomputeM(const float* __restrict__ Wq,
                          const float* __restrict__ Wk, int dir) {
    __shared__ float sq[64*64];
    __shared__ float sk[64*64];
    int t = threadIdx.x;
    for (int i = t; i < 4096; i += 256) { sq[i] = Wq[i]; sk[i] = Wk[i]; }
    __syncthreads();
    for (int i = t; i < 4096; i += 256) {
        int a = i >> 6, b = i & 63;
        float s = 0.f;
        #pragma unroll 16
        for (int c = 0; c < 64; c++) s += sq[c*64 + a] * sk[c*64 + b];
        g_Mt[dir*4096 + b*64 + a] = f2tf32(s);
    }
}

// ---------------------------------------------------------------------------
// Kernel 2: tensor-core axial attention (unchanged from R5)
// ---------------------------------------------------------------------------
#define ATTN_SMEM ((64*328*2 + 32*328 + 64*36)*4)   // 219136 B

__global__ __launch_bounds__(256)
void kattn(int dummy) {
    extern __shared__ float smem[];
    float* su = smem;                 // 64*328
    float* sd = su + 64*328;
    float* sP = sd + 64*328;          // 32*328
    float* sR = sP + 32*328;          // 64*36

    int tid  = threadIdx.x;
    int lane = tid & 31, warp = tid >> 5;
    int gid  = lane >> 2, tid4 = lane & 3;
    int b = blockIdx.x / HH, h = blockIdx.x % HH;
    const uint32_t* ub = g_utf + (size_t)b*CHW + (size_t)h*WW;
    const uint32_t* db = g_dtf + (size_t)b*CHW + (size_t)h*WW;

    for (int i = tid; i < 64*80; i += 256) {
        int c = i / 80, q4 = (i % 80) * 4;
        uint4 vu = *(const uint4*)(ub + (size_t)c*HW + q4);
        uint4 vd = *(const uint4*)(db + (size_t)c*HW + q4);
        *(uint4*)&su[c*328 + q4] = vu;
        *(uint4*)&sd[c*328 + q4] = vd;
    }

    for (int dir = 0; dir < 2; dir++) {
        const float* sQ = dir ? sd : su;
        const float* sV = dir ? su : sd;
        uint32_t* outg = g_buf[dir] + (size_t)b*CHW + (size_t)h*WW;

        const uint32_t* Mt = g_Mt + dir*4096;
        int bg = warp & 3, qh = warp >> 2;
        uint32_t am[8][4];
        {
            int r = bg*16 + gid;
            #pragma unroll
            for (int k = 0; k < 8; k++) {
                int c0 = k*8 + tid4;
                am[k][0] = Mt[r*64 + c0];
                am[k][1] = Mt[(r+8)*64 + c0];
                am[k][2] = Mt[r*64 + c0 + 4];
                am[k][3] = Mt[(r+8)*64 + c0 + 4];
            }
        }

        for (int q0 = 0; q0 < WW; q0 += 32) {
            __syncthreads();

            float4 rc[2];
            rc[0] = make_float4(0.f,0.f,0.f,0.f);
            rc[1] = make_float4(0.f,0.f,0.f,0.f);
            #pragma unroll
            for (int k = 0; k < 8; k++) {
                #pragma unroll
                for (int nt = 0; nt < 2; nt++) {
                    int qq = q0 + qh*16 + nt*8 + gid;
                    uint32_t b0 = fu(sQ[(k*8 + tid4)*328 + qq]);
                    uint32_t b1 = fu(sQ[(k*8 + tid4 + 4)*328 + qq]);
                    mma_tf32(rc[nt], am[k][0], am[k][1], am[k][2], am[k][3], b0, b1);
                }
            }
            #pragma unroll
            for (int nt = 0; nt < 2; nt++) {
                int q = qh*16 + nt*8 + 2*tid4;
                int bb = bg*16 + gid;
                *(uint2*)&sR[bb*36 + q]     = make_uint2(f2tf32(rc[nt].x), f2tf32(rc[nt].y));
                *(uint2*)&sR[(bb+8)*36 + q] = make_uint2(f2tf32(rc[nt].z), f2tf32(rc[nt].w));
            }
            __syncthreads();

            {
                int qg = warp >> 2, vg = warp & 3;
                float4 sc[10];
                #pragma unroll
                for (int nt = 0; nt < 10; nt++) sc[nt] = make_float4(0.f,0.f,0.f,0.f);
                #pragma unroll
                for (int k = 0; k < 8; k++) {
                    uint32_t a0 = fu(sR[(k*8 + tid4)*36 + qg*16 + gid]);
                    uint32_t a1 = fu(sR[(k*8 + tid4)*36 + qg*16 + gid + 8]);
                    uint32_t a2 = fu(sR[(k*8 + tid4 + 4)*36 + qg*16 + gid]);
                    uint32_t a3 = fu(sR[(k*8 + tid4 + 4)*36 + qg*16 + gid + 8]);
                    #pragma unroll
                    for (int nt = 0; nt < 10; nt++) {
                        int vv = vg*80 + nt*8 + gid;
                        uint32_t b0 = fu(sV[(k*8 + tid4)*328 + vv]);
                        uint32_t b1 = fu(sV[(k*8 + tid4 + 4)*328 + vv]);
                        mma_tf32(sc[nt], a0, a1, a2, a3, b0, b1);
                    }
                }
                #pragma unroll
                for (int nt = 0; nt < 10; nt++) {
                    int q = qg*16 + gid, v = vg*80 + nt*8 + 2*tid4;
                    *(float2*)&sP[q*328 + v]     = make_float2(sc[nt].x, sc[nt].y);
                    *(float2*)&sP[(q+8)*328 + v] = make_float2(sc[nt].z, sc[nt].w);
                }
            }
            __syncthreads();

            #pragma unroll
            for (int i = 0; i < 4; i++) {
                int row = warp*4 + i;
                float a[10];
                #pragma unroll
                for (int j = 0; j < 10; j++) a[j] = sP[row*328 + lane + 32*j];
                float m = a[0];
                #pragma unroll
                for (int j = 1; j < 10; j++) m = fmaxf(m, a[j]);
                #pragma unroll
                for (int o = 16; o > 0; o >>= 1) m = fmaxf(m, __shfl_xor_sync(~0u, m, o));
                float s = 0.f;
                #pragma unroll
                for (int j = 0; j < 10; j++) { a[j] = __expf(a[j] - m); s += a[j]; }
                #pragma unroll
                for (int o = 16; o > 0; o >>= 1) s += __shfl_xor_sync(~0u, s, o);
                float inv = 1.f / s;
                #pragma unroll
                for (int j = 0; j < 10; j++)
                    sP[row*328 + lane + 32*j] = __uint_as_float(f2tf32(a[j]*inv));
            }
            __syncthreads();

            {
                int cg = warp & 3, kh = warp >> 2;
                float4 oc[4];
                #pragma unroll
                for (int nt = 0; nt < 4; nt++) oc[nt] = make_float4(0.f,0.f,0.f,0.f);
                #pragma unroll
                for (int k = 0; k < 20; k++) {
                    int kb = kh*160 + k*8;
                    uint32_t a0 = fu(sV[(cg*16 + gid)*328 + kb + tid4]);
                    uint32_t a1 = fu(sV[(cg*16 + gid + 8)*328 + kb + tid4]);
                    uint32_t a2 = fu(sV[(cg*16 + gid)*328 + kb + tid4 + 4]);
                    uint32_t a3 = fu(sV[(cg*16 + gid + 8)*328 + kb + tid4 + 4]);
                    #pragma unroll
                    for (int nt = 0; nt < 4; nt++) {
                        uint32_t b0 = fu(sP[(nt*8 + gid)*328 + kb + tid4]);
                        uint32_t b1 = fu(sP[(nt*8 + gid)*328 + kb + tid4 + 4]);
                        mma_tf32(oc[nt], a0, a1, a2, a3, b0, b1);
                    }
                }
                if (kh == 0) {
                    #pragma unroll
                    for (int nt = 0; nt < 4; nt++) {
                        int c = cg*16 + gid, q = nt*8 + 2*tid4;
                        *(float2*)&sR[c*36 + q]     = make_float2(oc[nt].x, oc[nt].y);
                        *(float2*)&sR[(c+8)*36 + q] = make_float2(oc[nt].z, oc[nt].w);
                    }
                }
                __syncthreads();
                if (kh == 1) {
                    #pragma unroll
                    for (int nt = 0; nt < 4; nt++) {
                        int c = cg*16 + gid, q = nt*8 + 2*tid4;
                        float2 r0 = *(const float2*)&sR[c*36 + q];
                        float2 r1 = *(const float2*)&sR[(c+8)*36 + q];
                        uint2 w0 = make_uint2(f2tf32(oc[nt].x + r0.x), f2tf32(oc[nt].y + r0.y));
                        uint2 w1 = make_uint2(f2tf32(oc[nt].z + r1.x), f2tf32(oc[nt].w + r1.y));
                        *(uint2*)(outg + (size_t)c*HW + q0 + q)     = w0;
                        *(uint2*)(outg + (size_t)(c+8)*HW + q0 + q) = w1;
                    }
                }
            }
        }
        __syncthreads();
    }
}

// ---------------------------------------------------------------------------
// Kernel 3: tf32 implicit-GEMM 3x3 conv, double-buffered cp.async pipeline.
// Block = 512 thr, tile 64x x 8y, both streams via blockIdx.z = (s<<1)|b.
// Input smem plane stride 728 (=24 mod 32 -> conflict-free B LDS.32).
// ---------------------------------------------------------------------------
#define PLANE 728
#define SIN_U32 (16*PLANE)              // 11648
#define SW_U32  (9*64*18)               // 10368
#define STAGE_U32 (SIN_U32 + SW_U32)    // 22016
#define CONV_SMEM (STAGE_U32*2*4)       // 176128 bytes

template<int CIN, bool FUSE>
__global__ __launch_bounds__(512, 1)
void kconv(const uint32_t* __restrict__ in1u, const uint32_t* __restrict__ in1d,
           const uint32_t* __restrict__ in2u, const uint32_t* __restrict__ in2d,
           const uint32_t* __restrict__ wpu,  const uint32_t* __restrict__ wpd,
           void* __restrict__ outu, void* __restrict__ outd) {
    extern __shared__ uint32_t csm[];

    int tid  = threadIdx.x;
    int lane = tid & 31, warp = tid >> 5;
    int x0 = blockIdx.x * 64;
    int y0 = blockIdx.y * 8;
    int z  = blockIdx.z;
    int b  = z & 1, st = z >> 1;
    size_t bCHW = (size_t)b*CHW;

    const uint32_t* in1 = st ? in1d : in1u;
    const uint32_t* in2 = st ? in2d : in2u;
    const uint32_t* wp  = st ? wpd  : wpu;
    void* outv          = st ? outd : outu;

    int warp_o = warp & 1;
    int warp_y = warp >> 1;         // 0..7
    int lq = lane >> 2;
    int lr = lane & 3;

    uint32_t s_base = (uint32_t)__cvta_generic_to_shared(csm);

    const int NCH = CIN/16;

    // ---- staging helpers ----
    auto stage = [&](int cb, int bufi) {
        uint32_t sb = s_base + bufi*STAGE_U32*4;
        // input: 16 ch x 10 rows x 18 quads
        for (int i = tid; i < 2880; i += 512) {
            int c   = i / 180;
            int rem = i % 180;
            int r   = rem / 18;
            int q   = rem % 18;
            int gy = y0 + r - 1;
            int gx = x0 - 4 + q*4;
            uint32_t ok = (gy >= 0 && gy < HH && gx >= 0 && gx < WW) ? 16u : 0u;
            int cg = cb*16 + c;
            const uint32_t* plane;
            if (CIN == 128 && cg >= 64) plane = in2 + bCHW + (size_t)(cg - 64)*HW;
            else                        plane = in1 + bCHW + (size_t)cg*HW;
            const uint32_t* gsrc = ok ? (plane + gy*WW + gx) : plane;
            cp16(sb + (c*PLANE + r*72 + q*4)*4, gsrc, ok);
        }
        // weights
        const uint32_t* wsrc = wp + cb*SW_U32;
        for (int i = tid; i < SW_U32/4; i += 512)
            cp16(sb + (SIN_U32 + i*4)*4, wsrc + i*4, 16);
    };

    float4 acc[2][8];
    #pragma unroll
    for (int mt = 0; mt < 2; mt++)
        #pragma unroll
        for (int nt = 0; nt < 8; nt++) acc[mt][nt] = make_float4(0.f,0.f,0.f,0.f);

    stage(0, 0);
    asm volatile("cp.async.commit_group;" ::: "memory");

    for (int cb = 0; cb < NCH; cb++) {
        if (cb + 1 < NCH) {
            stage(cb + 1, (cb + 1) & 1);
            asm volatile("cp.async.commit_group;" ::: "memory");
            asm volatile("cp.async.wait_group 1;" ::: "memory");
        } else {
            asm volatile("cp.async.wait_group 0;" ::: "memory");
        }
        __syncthreads();

        const uint32_t* sin_ = csm + (cb & 1)*STAGE_U32;
        const uint32_t* sw_  = sin_ + SIN_U32;

        #pragma unroll
        for (int t = 0; t < 9; t++) {
            int ky = t/3, kx = t - ky*3;
            int row = warp_y + ky;
            int bbase = row*72 + kx + 3 + lq;
            #pragma unroll
            for (int s = 0; s < 2; s++) {
                int aoff = (t*64 + warp_o*32)*18 + s*8 + 2*lr;
                uint2 a00 = *(const uint2*)&sw_[aoff + lq*18];
                uint2 a01 = *(const uint2*)&sw_[aoff + (lq+8)*18];
                uint2 a10 = *(const uint2*)&sw_[aoff + (lq+16)*18];
                uint2 a11 = *(const uint2*)&sw_[aoff + (lq+24)*18];
                int p0 = (s*8 + lr)*PLANE + bbase;
                int p1 = p0 + 4*PLANE;
                #pragma unroll
                for (int nt = 0; nt < 8; nt++) {
                    uint32_t b0 = sin_[p0 + 8*nt];
                    uint32_t b1 = sin_[p1 + 8*nt];
                    mma_tf32(acc[0][nt], a00.x, a01.x, a00.y, a01.y, b0, b1);
                    mma_tf32(acc[1][nt], a10.x, a11.x, a10.y, a11.y, b0, b1);
                }
            }
        }
        __syncthreads();
    }

    // ---- writeback ----
    int y = y0 + warp_y;
    #pragma unroll
    for (int mt = 0; mt < 2; mt++) {
        int o_lo = warp_o*32 + mt*16 + lq;
        #pragma unroll
        for (int nt = 0; nt < 8; nt++) {
            int x = x0 + nt*8 + 2*lr;
            float4 v = acc[mt][nt];
            size_t off = bCHW + (size_t)o_lo*HW + (size_t)y*WW + x;
            if (FUSE) {
                uint32_t* outp = (uint32_t*)outv;
                uint2 r0 = make_uint2(f2tf32(fmaxf(v.x, 0.f)), f2tf32(fmaxf(v.y, 0.f)));
                uint2 r1 = make_uint2(f2tf32(fmaxf(v.z, 0.f)), f2tf32(fmaxf(v.w, 0.f)));
                *(uint2*)(outp + off)            = r0;
                *(uint2*)(outp + off + 8*HW)     = r1;
            } else {
                float* outp = (float*)outv;
                *(float2*)(outp + off)           = make_float2(v.x, v.y);
                *(float2*)(outp + off + 8*HW)    = make_float2(v.z, v.w);
            }
        }
    }
}

// ---------------------------------------------------------------------------
extern "C" void kernel_launch(void* const* d_in, const int* in_sizes, int n_in,
                              void* d_out, int out_size) {
    const float* u   = (const float*)d_in[0];
    const float* d   = (const float*)d_in[1];
    const float* Wu1 = (const float*)d_in[2];
    const float* Wu2 = (const float*)d_in[3];
    const float* Wd1 = (const float*)d_in[4];
    const float* Wd2 = (const float*)d_in[5];
    const float* W1a = (const float*)d_in[6];
    const float* W1b = (const float*)d_in[7];
    const float* W2a = (const float*)d_in[8];
    const float* W2b = (const float*)d_in[9];
    float* out = (float*)d_out;

    cudaFuncSetAttribute(kattn, cudaFuncAttributeMaxDynamicSharedMemorySize, ATTN_SMEM);
    cudaFuncSetAttribute(kconv<128, true>,  cudaFuncAttributeMaxDynamicSharedMemorySize, CONV_SMEM);
    cudaFuncSetAttribute(kconv<64, false>,  cudaFuncAttributeMaxDynamicSharedMemorySize, CONV_SMEM);

    uint32_t *pbuf0, *pbuf1, *pt0, *pt1, *putf, *pdtf;
    uint32_t *pw1a, *pw2a, *pw1b, *pw2b;
    cudaGetSymbolAddress((void**)&pbuf0, g_buf);   pbuf1 = pbuf0 + TENSOR_ELEMS;
    cudaGetSymbolAddress((void**)&pt0,   g_t);     pt1   = pt0   + TENSOR_ELEMS;
    cudaGetSymbolAddress((void**)&putf,  g_utf);
    cudaGetSymbolAddress((void**)&pdtf,  g_dtf);
    cudaGetSymbolAddress((void**)&pw1a,  g_wp1a);
    cudaGetSymbolAddress((void**)&pw2a,  g_wp2a);
    cudaGetSymbolAddress((void**)&pw1b,  g_wp1b);
    cudaGetSymbolAddress((void**)&pw2b,  g_wp2b);

    // prep
    kprepin<<<2048, 256>>>(u, d);
    kprepw<<<(8*9*64*18 + 255)/256, 256>>>(W1a, pw1a, 128);
    kprepw<<<(8*9*64*18 + 255)/256, 256>>>(W2a, pw2a, 128);
    kprepw<<<(4*9*64*18 + 255)/256, 256>>>(W1b, pw1b, 64);
    kprepw<<<(4*9*64*18 + 255)/256, 256>>>(W2b, pw2b, 64);
    kcomputeM<<<1, 256>>>(Wu1, Wd2, 0);
    kcomputeM<<<1, 256>>>(Wd1, Wu2, 1);

    // attention (tensor core) -> tf32 buffers
    kattn<<<BB*HH, 256, ATTN_SMEM>>>(0);

    // conv1 + relu (both streams in one launch), then conv2
    dim3 grid(WW/64, HH/8, 4);
    kconv<128, true><<<grid, 512, CONV_SMEM>>>(putf, pdtf, pbuf0, pbuf1,
                                               pw1a, pw2a, pt0, pt1);
    kconv<64, false><<<grid, 512, CONV_SMEM>>>(pt0, pt1, pt0, pt1,
                                               pw1b, pw2b, out, out + TENSOR_ELEMS);
}